// round 7
// baseline (speedup 1.0000x reference)
#include <cuda_runtime.h>
#include <cstdint>

#define N_NODES 262144
#define DIM     256
#define HID     128
#define NGRAPH  2048
#define TROWS   256           // rows per tile (32 per warp)
#define NTILES  1024          // N_NODES / TROWS
#define SGRID   152

// smem layout for score kernel
#define WSF_BYTES   131072    // uint32 wsf[32 ksteps][16 ntiles][32 lanes][2]
#define XS_BYTES    73728     // float xs[2][256][36]
#define B1F_BYTES   4096      // float b1f[16][32][2]
#define W2F_BYTES   4096
#define SMEM_BYTES  (WSF_BYTES + XS_BYTES + B1F_BYTES + W2F_BYTES)   // 212992

__device__ float g_scores[N_NODES];

// ---------------------------------------------------------------------------
__device__ __forceinline__ uint32_t f2tf32(float f) {
    uint32_t u;
    asm("cvt.rna.tf32.f32 %0, %1;" : "=r"(u) : "f"(f));
    return u;
}

__device__ __forceinline__ void mma_tf32(float* c,
                                         uint32_t a0, uint32_t a1, uint32_t a2, uint32_t a3,
                                         uint32_t b0, uint32_t b1) {
    asm volatile(
        "mma.sync.aligned.m16n8k8.row.col.f32.tf32.tf32.f32 "
        "{%0,%1,%2,%3}, {%4,%5,%6,%7}, {%8,%9}, {%0,%1,%2,%3};"
        : "+f"(c[0]), "+f"(c[1]), "+f"(c[2]), "+f"(c[3])
        : "r"(a0), "r"(a1), "r"(a2), "r"(a3), "r"(b0), "r"(b1));
}

__device__ __forceinline__ void cp16(uint32_t dst, const void* src) {
    asm volatile("cp.async.cg.shared.global [%0], [%1], 16;" :: "r"(dst), "l"(src));
}
#define CP_COMMIT() asm volatile("cp.async.commit_group;")
#define CP_WAIT1()  asm volatile("cp.async.wait_group 1;")

__device__ __forceinline__ int lower_bound_i(const int* __restrict__ b, int n, int key) {
    int lo = 0, hi = n;
    while (lo < hi) {
        int mid = (lo + hi) >> 1;
        if (b[mid] < key) lo = mid + 1; else hi = mid;
    }
    return lo;
}

__device__ __forceinline__ float warp_max(float v) {
    #pragma unroll
    for (int o = 16; o; o >>= 1) v = fmaxf(v, __shfl_xor_sync(0xffffffffu, v, o));
    return v;
}
__device__ __forceinline__ float warp_sum(float v) {
    #pragma unroll
    for (int o = 16; o; o >>= 1) v += __shfl_xor_sync(0xffffffffu, v, o);
    return v;
}

// ---------------------------------------------------------------------------
// Kernel 1: scores[i] = b2 + sum_j W2[j] * relu(b1[j] + sum_k x[i][k]*W1[k][j])
// Persistent blocks; tile = 256 nodes; each warp computes 32 nodes x 128 j via
// tf32 mma.sync m16n8k8 (two row-sets share every B-fragment load -> halved
// smem B traffic). x staged via cp.async double-buffer.
// ---------------------------------------------------------------------------
__global__ void __launch_bounds__(256, 1)
score_kernel(const float* __restrict__ x,
             const float* __restrict__ W1,
             const float* __restrict__ b1,
             const float* __restrict__ W2,
             const float* __restrict__ b2) {
    extern __shared__ __align__(16) unsigned char smem[];
    uint32_t* wsf = (uint32_t*)smem;                          // [ks][nt][lane][2]
    float*    xs  = (float*)(smem + WSF_BYTES);               // [2][256][36]
    float*    b1f = (float*)(smem + WSF_BYTES + XS_BYTES);    // [nt][lane][2]
    float*    w2f = b1f + 1024;
    const uint32_t xs_u32 = (uint32_t)__cvta_generic_to_shared(xs);

    const int tid  = threadIdx.x;
    const int lane = tid & 31;
    const int warp = tid >> 5;

    // --- stage W1 as tf32 B-fragments: b0 = W1[ks*8 + (lane&3)][nt*8 + lane/4]
    for (int i = tid; i < 32 * 16 * 32; i += 256) {
        int l = i & 31, nt = (i >> 5) & 15, ks = i >> 9;
        int col = nt * 8 + (l >> 2);
        int r0  = ks * 8 + (l & 3);
        wsf[2 * i + 0] = f2tf32(W1[r0 * HID + col]);
        wsf[2 * i + 1] = f2tf32(W1[(r0 + 4) * HID + col]);
    }
    // --- stage b1 / W2 in C-fragment column order: cols nt*8 + 2*(lane&3) {,+1}
    for (int i = tid; i < 16 * 32; i += 256) {
        int l = i & 31, nt = i >> 5;
        int c0 = nt * 8 + 2 * (l & 3);
        b1f[2 * i + 0] = b1[c0];
        b1f[2 * i + 1] = b1[c0 + 1];
        w2f[2 * i + 0] = W2[c0];
        w2f[2 * i + 1] = W2[c0 + 1];
    }
    const float b2v = b2[0];

    const int grid = gridDim.x;
    const int srow = tid >> 3;          // staging row base 0..31 (covers +32q, q=0..7)
    const int scol = (tid & 7) * 4;     // staging col offset within 32-wide chunk

    // --- prologue: issue chunk 0 of first tile into buffer 0
    {
        const float* src = x + ((size_t)(blockIdx.x * TROWS + srow)) * DIM + scol;
        uint32_t dst = xs_u32 + (uint32_t)(srow * 36 + scol) * 4u;
        #pragma unroll
        for (int q = 0; q < 8; q++)
            cp16(dst + q * (32 * 36 * 4), src + (size_t)q * 32 * DIM);
    }
    CP_COMMIT();
    __syncthreads();

    const int rA = warp * 32 + (lane >> 2);   // A-frag row (set0); set1 = +16
    const int t4 = lane & 3;

    for (int tile = blockIdx.x; tile < NTILES; tile += grid) {
        float c0[16][4], c1[16][4];
        #pragma unroll
        for (int nt = 0; nt < 16; nt++)
            #pragma unroll
            for (int q = 0; q < 4; q++) { c0[nt][q] = 0.0f; c1[nt][q] = 0.0f; }

        #pragma unroll 1
        for (int kc = 0; kc < 8; kc++) {
            const int cur = kc & 1;
            // issue next chunk into other buffer (next tile's chunk 0 when kc==7)
            int ptile = (kc < 7) ? tile : (tile + grid);
            int pkc   = (kc + 1) & 7;
            if (ptile < NTILES) {
                const float* src = x + ((size_t)(ptile * TROWS + srow)) * DIM + pkc * 32 + scol;
                uint32_t dst = xs_u32 + (uint32_t)((cur ^ 1) * (256 * 36) + srow * 36 + scol) * 4u;
                #pragma unroll
                for (int q = 0; q < 8; q++)
                    cp16(dst + q * (32 * 36 * 4), src + (size_t)q * 32 * DIM);
            }
            CP_COMMIT();
            CP_WAIT1();
            __syncthreads();

            // compute 4 k-steps from current buffer
            const float* xb = xs + cur * (256 * 36);
            #pragma unroll
            for (int ksl = 0; ksl < 4; ksl++) {
                int k0 = ksl * 8;
                const float* rp = xb + rA * 36 + k0 + t4;
                uint32_t a0 = f2tf32(rp[0]);
                uint32_t a1 = f2tf32(rp[8 * 36]);
                uint32_t a2 = f2tf32(rp[4]);
                uint32_t a3 = f2tf32(rp[8 * 36 + 4]);
                uint32_t a4 = f2tf32(rp[16 * 36]);
                uint32_t a5 = f2tf32(rp[24 * 36]);
                uint32_t a6 = f2tf32(rp[16 * 36 + 4]);
                uint32_t a7 = f2tf32(rp[24 * 36 + 4]);
                int ks = kc * 4 + ksl;
                const uint32_t* wb = wsf + (ks * 512 + lane) * 2;
                #pragma unroll
                for (int nt = 0; nt < 16; nt++) {
                    uint32_t bb0 = wb[nt * 64];
                    uint32_t bb1 = wb[nt * 64 + 1];
                    mma_tf32(c0[nt], a0, a1, a2, a3, bb0, bb1);
                    mma_tf32(c1[nt], a4, a5, a6, a7, bb0, bb1);
                }
            }
            __syncthreads();
        }

        // --- epilogue: bias + relu + dot with W2, reduce over j
        float p0 = 0.0f, p8 = 0.0f, p16 = 0.0f, p24 = 0.0f;
        #pragma unroll
        for (int nt = 0; nt < 16; nt++) {
            int bi = (nt * 32 + lane) * 2;
            float q0 = b1f[bi], q1 = b1f[bi + 1];
            float w0 = w2f[bi], w1 = w2f[bi + 1];
            p0  += fmaxf(c0[nt][0] + q0, 0.0f) * w0 + fmaxf(c0[nt][1] + q1, 0.0f) * w1;
            p8  += fmaxf(c0[nt][2] + q0, 0.0f) * w0 + fmaxf(c0[nt][3] + q1, 0.0f) * w1;
            p16 += fmaxf(c1[nt][0] + q0, 0.0f) * w0 + fmaxf(c1[nt][1] + q1, 0.0f) * w1;
            p24 += fmaxf(c1[nt][2] + q0, 0.0f) * w0 + fmaxf(c1[nt][3] + q1, 0.0f) * w1;
        }
        p0  += __shfl_xor_sync(0xffffffffu, p0, 1);
        p0  += __shfl_xor_sync(0xffffffffu, p0, 2);
        p8  += __shfl_xor_sync(0xffffffffu, p8, 1);
        p8  += __shfl_xor_sync(0xffffffffu, p8, 2);
        p16 += __shfl_xor_sync(0xffffffffu, p16, 1);
        p16 += __shfl_xor_sync(0xffffffffu, p16, 2);
        p24 += __shfl_xor_sync(0xffffffffu, p24, 1);
        p24 += __shfl_xor_sync(0xffffffffu, p24, 2);
        if ((lane & 3) == 0) {
            int row = tile * TROWS + warp * 32 + (lane >> 2);
            g_scores[row]      = p0  + b2v;
            g_scores[row + 8]  = p8  + b2v;
            g_scores[row + 16] = p16 + b2v;
            g_scores[row + 24] = p24 + b2v;
        }
    }
}

// ---------------------------------------------------------------------------
// Kernel 2: fused segment softmax + weighted pooling.
// One block per graph (batch sorted). Pass1 max, pass2 exp+sum (weights cached
// in smem), pass3 float4 weighted accumulation (64 threads/row, 4 row-groups).
// ---------------------------------------------------------------------------
__global__ void __launch_bounds__(256)
pool_kernel(const int* __restrict__ batch,
            const float* __restrict__ x,
            float* __restrict__ out) {
    const int g = blockIdx.x;
    const int tid = threadIdx.x;
    const int lane = tid & 31, wid = tid >> 5;
    __shared__ int sse[2];
    __shared__ float red[8];
    __shared__ __align__(16) float sw[1024];
    __shared__ __align__(16) float sred[4][256];

    if (tid < 2) sse[tid] = lower_bound_i(batch, N_NODES, g + tid);
    __syncthreads();
    const int start = sse[0], end = sse[1];
    const int len = end - start;
    const bool fits = (len <= 1024);

    // pass 1: max
    float m = -1e30f;
    for (int i = start + tid; i < end; i += 256) m = fmaxf(m, g_scores[i]);
    m = warp_max(m);
    if (lane == 0) red[wid] = m;
    __syncthreads();
    if (wid == 0) {
        float v = (lane < 8) ? red[lane] : -1e30f;
        v = warp_max(v);
        if (lane == 0) red[0] = v;
    }
    __syncthreads();
    const float M = red[0];
    __syncthreads();

    // pass 2: exp + sum (cache unnormalized weights when they fit)
    float s = 0.0f;
    for (int i = start + tid; i < end; i += 256) {
        float e = __expf(g_scores[i] - M);
        if (fits) sw[i - start] = e;
        s += e;
    }
    s = warp_sum(s);
    if (lane == 0) red[wid] = s;
    __syncthreads();
    if (wid == 0) {
        float v = (lane < 8) ? red[lane] : 0.0f;
        v = warp_sum(v);
        if (lane == 0) red[0] = v;
    }
    __syncthreads();
    const float inv = (len > 0) ? (1.0f / red[0]) : 0.0f;

    // pass 3: weighted float4 accumulation
    const int c4 = (tid & 63) * 4;
    const int rg = tid >> 6;
    float ax = 0.0f, ay = 0.0f, az = 0.0f, aw = 0.0f;

    if (fits) {
        __syncthreads();
        for (int r = start + rg; r < end; r += 4) {
            float w = sw[r - start] * inv;
            float4 v = *(const float4*)(x + (size_t)r * DIM + c4);
            ax = fmaf(w, v.x, ax);
            ay = fmaf(w, v.y, ay);
            az = fmaf(w, v.z, az);
            aw = fmaf(w, v.w, aw);
        }
    } else {
        for (int base = start; base < end; base += 1024) {
            int mlen = end - base; if (mlen > 1024) mlen = 1024;
            __syncthreads();
            for (int j = tid; j < mlen; j += 256) sw[j] = __expf(g_scores[base + j] - M);
            __syncthreads();
            for (int r = base + rg; r < base + mlen; r += 4) {
                float w = sw[r - base] * inv;
                float4 v = *(const float4*)(x + (size_t)r * DIM + c4);
                ax = fmaf(w, v.x, ax);
                ay = fmaf(w, v.y, ay);
                az = fmaf(w, v.z, az);
                aw = fmaf(w, v.w, aw);
            }
        }
    }

    __syncthreads();
    sred[rg][c4 + 0] = ax;
    sred[rg][c4 + 1] = ay;
    sred[rg][c4 + 2] = az;
    sred[rg][c4 + 3] = aw;
    __syncthreads();
    float v = sred[0][tid] + sred[1][tid] + sred[2][tid] + sred[3][tid];
    out[g * DIM + tid] = v;
}

// ---------------------------------------------------------------------------
extern "C" void kernel_launch(void* const* d_in, const int* in_sizes, int n_in,
                              void* d_out, int out_size) {
    const float* x     = (const float*)d_in[0];
    const int*   batch = (const int*)d_in[1];
    // d_in[2] = num_graphs (constant 2048, unused)
    const float* W1 = (const float*)d_in[3];
    const float* b1 = (const float*)d_in[4];
    const float* W2 = (const float*)d_in[5];
    const float* b2 = (const float*)d_in[6];
    float* out = (float*)d_out;

    cudaFuncSetAttribute(score_kernel, cudaFuncAttributeMaxDynamicSharedMemorySize, SMEM_BYTES);
    score_kernel<<<SGRID, 256, SMEM_BYTES>>>(x, W1, b1, W2, b2);
    pool_kernel<<<NGRAPH, 256>>>(batch, x, out);
}

// round 9
// speedup vs baseline: 1.2428x; 1.2428x over previous
#include <cuda_runtime.h>
#include <cstdint>

#define N_NODES 262144
#define DIM     256
#define HID     128
#define NGRAPH  2048
#define NTILES  2048          // N_NODES / 128
#define SGRID   152

// smem layout for score kernel
#define WSF_BYTES   131072    // uint32 wsf[32 ksteps][16 ntiles][32 lanes][2]
#define XS_BYTES    36864     // float xs[2][128][36]
#define B1F_BYTES   4096      // float b1f[16][32][2]
#define W2F_BYTES   4096
#define SMEM_BYTES  (WSF_BYTES + XS_BYTES + B1F_BYTES + W2F_BYTES)   // 176128

__device__ float g_scores[N_NODES];

// ---------------------------------------------------------------------------
__device__ __forceinline__ uint32_t f2tf32(float f) {
    uint32_t u;
    asm("cvt.rna.tf32.f32 %0, %1;" : "=r"(u) : "f"(f));
    return u;
}

__device__ __forceinline__ void mma_tf32(float* c,
                                         uint32_t a0, uint32_t a1, uint32_t a2, uint32_t a3,
                                         uint32_t b0, uint32_t b1) {
    asm volatile(
        "mma.sync.aligned.m16n8k8.row.col.f32.tf32.tf32.f32 "
        "{%0,%1,%2,%3}, {%4,%5,%6,%7}, {%8,%9}, {%0,%1,%2,%3};"
        : "+f"(c[0]), "+f"(c[1]), "+f"(c[2]), "+f"(c[3])
        : "r"(a0), "r"(a1), "r"(a2), "r"(a3), "r"(b0), "r"(b1));
}

__device__ __forceinline__ int lower_bound_i(const int* __restrict__ b, int n, int key) {
    int lo = 0, hi = n;
    while (lo < hi) {
        int mid = (lo + hi) >> 1;
        if (b[mid] < key) lo = mid + 1; else hi = mid;
    }
    return lo;
}

__device__ __forceinline__ float warp_max(float v) {
    #pragma unroll
    for (int o = 16; o; o >>= 1) v = fmaxf(v, __shfl_xor_sync(0xffffffffu, v, o));
    return v;
}
__device__ __forceinline__ float warp_sum(float v) {
    #pragma unroll
    for (int o = 16; o; o >>= 1) v += __shfl_xor_sync(0xffffffffu, v, o);
    return v;
}

// ---------------------------------------------------------------------------
// Kernel 1: scores[i] = b2 + sum_j W2[j] * relu(b1[j] + sum_k x[i][k]*W1[k][j])
// (R5 structure: 128-row tiles, 16 rows/warp, register-prefetch double buffer.
//  Known-good: 119.4us, 144 regs, no spills.)
// ---------------------------------------------------------------------------
__global__ void __launch_bounds__(256, 1)
score_kernel(const float* __restrict__ x,
             const float* __restrict__ W1,
             const float* __restrict__ b1,
             const float* __restrict__ W2,
             const float* __restrict__ b2) {
    extern __shared__ __align__(16) unsigned char smem[];
    uint32_t* wsf = (uint32_t*)smem;                          // [ks][nt][lane][2]
    float*    xs  = (float*)(smem + WSF_BYTES);               // [2][128][36]
    float*    b1f = (float*)(smem + WSF_BYTES + XS_BYTES);    // [nt][lane][2]
    float*    w2f = b1f + 1024;

    const int tid  = threadIdx.x;
    const int lane = tid & 31;
    const int warp = tid >> 5;

    // --- stage W1 as tf32 B-fragments: b0 = W1[ks*8 + (lane&3)][nt*8 + lane/4]
    for (int i = tid; i < 32 * 16 * 32; i += 256) {
        int l = i & 31, nt = (i >> 5) & 15, ks = i >> 9;
        int col = nt * 8 + (l >> 2);
        int r0  = ks * 8 + (l & 3);
        wsf[2 * i + 0] = f2tf32(W1[r0 * HID + col]);
        wsf[2 * i + 1] = f2tf32(W1[(r0 + 4) * HID + col]);
    }
    // --- stage b1 / W2 in C-fragment column order: cols nt*8 + 2*(lane&3) {,+1}
    for (int i = tid; i < 16 * 32; i += 256) {
        int l = i & 31, nt = i >> 5;
        int c0 = nt * 8 + 2 * (l & 3);
        b1f[2 * i + 0] = b1[c0];
        b1f[2 * i + 1] = b1[c0 + 1];
        w2f[2 * i + 0] = W2[c0];
        w2f[2 * i + 1] = W2[c0 + 1];
    }
    const float b2v = b2[0];

    const int grid = gridDim.x;
    const int srow = tid >> 3;        // staging row 0..31 (thread covers +0,+32,+64,+96)
    const int scol = (tid & 7) * 4;   // staging col offset within 32-wide chunk

    // --- prologue: chunk 0 of first tile into buffer 0
    {
        int t0 = blockIdx.x;
        if (t0 < NTILES) {
            #pragma unroll
            for (int q = 0; q < 4; q++) {
                int row = srow + 32 * q;
                float4 v = *(const float4*)(x + (t0 * 128 + row) * DIM + scol);
                *(float4*)(xs + row * 36 + scol) = v;
            }
        }
    }
    __syncthreads();

    const int rA = warp * 16 + (lane >> 2);   // A-frag row within tile
    const int t4 = lane & 3;

    for (int tile = blockIdx.x; tile < NTILES; tile += grid) {
        float c[16][4];
        #pragma unroll
        for (int nt = 0; nt < 16; nt++)
            #pragma unroll
            for (int q = 0; q < 4; q++) c[nt][q] = 0.0f;

        #pragma unroll 1
        for (int kc = 0; kc < 8; kc++) {
            // prefetch next chunk (next tile's chunk 0 when kc==7)
            int ptile = (kc < 7) ? tile : (tile + grid);
            int pkc   = (kc + 1) & 7;
            bool pv   = (ptile < NTILES);
            float4 pr[4];
            if (pv) {
                #pragma unroll
                for (int q = 0; q < 4; q++) {
                    int row = srow + 32 * q;
                    pr[q] = *(const float4*)(x + (ptile * 128 + row) * DIM + pkc * 32 + scol);
                }
            }

            // compute 4 k-steps from current buffer
            const float* xb = xs + (kc & 1) * (128 * 36);
            #pragma unroll
            for (int ksl = 0; ksl < 4; ksl++) {
                int k0 = ksl * 8;
                uint32_t a0 = f2tf32(xb[rA * 36 + k0 + t4]);
                uint32_t a1 = f2tf32(xb[(rA + 8) * 36 + k0 + t4]);
                uint32_t a2 = f2tf32(xb[rA * 36 + k0 + t4 + 4]);
                uint32_t a3 = f2tf32(xb[(rA + 8) * 36 + k0 + t4 + 4]);
                int ks = kc * 4 + ksl;
                const uint32_t* wb = wsf + (ks * 512 + lane) * 2;
                #pragma unroll
                for (int nt = 0; nt < 16; nt++) {
                    uint32_t bb0 = wb[nt * 64];
                    uint32_t bb1 = wb[nt * 64 + 1];
                    mma_tf32(c[nt], a0, a1, a2, a3, bb0, bb1);
                }
            }

            // store prefetched chunk into other buffer
            if (pv) {
                float* xd = xs + ((kc + 1) & 1) * (128 * 36);
                #pragma unroll
                for (int q = 0; q < 4; q++) {
                    int row = srow + 32 * q;
                    *(float4*)(xd + row * 36 + scol) = pr[q];
                }
            }
            __syncthreads();
        }

        // --- epilogue: bias + relu + dot with W2, reduce over j
        float p0 = 0.0f, p8 = 0.0f;
        #pragma unroll
        for (int nt = 0; nt < 16; nt++) {
            int bi = (nt * 32 + lane) * 2;
            float q0 = b1f[bi], q1 = b1f[bi + 1];
            float w0 = w2f[bi], w1 = w2f[bi + 1];
            p0 += fmaxf(c[nt][0] + q0, 0.0f) * w0 + fmaxf(c[nt][1] + q1, 0.0f) * w1;
            p8 += fmaxf(c[nt][2] + q0, 0.0f) * w0 + fmaxf(c[nt][3] + q1, 0.0f) * w1;
        }
        p0 += __shfl_xor_sync(0xffffffffu, p0, 1);
        p0 += __shfl_xor_sync(0xffffffffu, p0, 2);
        p8 += __shfl_xor_sync(0xffffffffu, p8, 1);
        p8 += __shfl_xor_sync(0xffffffffu, p8, 2);
        if ((lane & 3) == 0) {
            int row = tile * 128 + warp * 16 + (lane >> 2);
            g_scores[row]     = p0 + b2v;
            g_scores[row + 8] = p8 + b2v;
        }
    }
}

// ---------------------------------------------------------------------------
// Kernel 2: fused segment softmax + weighted pooling.
// One block per graph (batch sorted). Pass1 max, pass2 exp+sum (weights cached
// in smem), pass3: 4-way unrolled float4 weighted accumulation (MLP=4).
// ---------------------------------------------------------------------------
__global__ void __launch_bounds__(256)
pool_kernel(const int* __restrict__ batch,
            const float* __restrict__ x,
            float* __restrict__ out) {
    const int g = blockIdx.x;
    const int tid = threadIdx.x;
    const int lane = tid & 31, wid = tid >> 5;
    __shared__ int sse[2];
    __shared__ float red[8];
    __shared__ __align__(16) float sw[1024];
    __shared__ __align__(16) float sred[4][256];

    if (tid < 2) sse[tid] = lower_bound_i(batch, N_NODES, g + tid);
    __syncthreads();
    const int start = sse[0], end = sse[1];
    const int len = end - start;
    const bool fits = (len <= 1024);

    // pass 1: max
    float m = -1e30f;
    for (int i = start + tid; i < end; i += 256) m = fmaxf(m, g_scores[i]);
    m = warp_max(m);
    if (lane == 0) red[wid] = m;
    __syncthreads();
    if (wid == 0) {
        float v = (lane < 8) ? red[lane] : -1e30f;
        v = warp_max(v);
        if (lane == 0) red[0] = v;
    }
    __syncthreads();
    const float M = red[0];
    __syncthreads();

    // pass 2: exp + sum (cache unnormalized weights when they fit)
    float s = 0.0f;
    for (int i = start + tid; i < end; i += 256) {
        float e = __expf(g_scores[i] - M);
        if (fits) sw[i - start] = e;
        s += e;
    }
    s = warp_sum(s);
    if (lane == 0) red[wid] = s;
    __syncthreads();
    if (wid == 0) {
        float v = (lane < 8) ? red[lane] : 0.0f;
        v = warp_sum(v);
        if (lane == 0) red[0] = v;
    }
    __syncthreads();
    const float inv = (len > 0) ? (1.0f / red[0]) : 0.0f;

    // pass 3: weighted float4 accumulation, 4 rows in flight per thread
    const int c4 = (tid & 63) * 4;
    const int rg = tid >> 6;
    float4 acc0 = make_float4(0.f, 0.f, 0.f, 0.f);
    float4 acc1 = make_float4(0.f, 0.f, 0.f, 0.f);
    float4 acc2 = make_float4(0.f, 0.f, 0.f, 0.f);
    float4 acc3 = make_float4(0.f, 0.f, 0.f, 0.f);

    if (fits) {
        __syncthreads();
        int r = start + rg;
        for (; r + 12 < end; r += 16) {
            const float* xp = x + (size_t)r * DIM + c4;
            float w0 = sw[r - start]      * inv;
            float w1 = sw[r - start + 4]  * inv;
            float w2 = sw[r - start + 8]  * inv;
            float w3 = sw[r - start + 12] * inv;
            float4 v0 = *(const float4*)(xp);
            float4 v1 = *(const float4*)(xp + 4 * DIM);
            float4 v2 = *(const float4*)(xp + 8 * DIM);
            float4 v3 = *(const float4*)(xp + 12 * DIM);
            acc0.x = fmaf(w0, v0.x, acc0.x); acc0.y = fmaf(w0, v0.y, acc0.y);
            acc0.z = fmaf(w0, v0.z, acc0.z); acc0.w = fmaf(w0, v0.w, acc0.w);
            acc1.x = fmaf(w1, v1.x, acc1.x); acc1.y = fmaf(w1, v1.y, acc1.y);
            acc1.z = fmaf(w1, v1.z, acc1.z); acc1.w = fmaf(w1, v1.w, acc1.w);
            acc2.x = fmaf(w2, v2.x, acc2.x); acc2.y = fmaf(w2, v2.y, acc2.y);
            acc2.z = fmaf(w2, v2.z, acc2.z); acc2.w = fmaf(w2, v2.w, acc2.w);
            acc3.x = fmaf(w3, v3.x, acc3.x); acc3.y = fmaf(w3, v3.y, acc3.y);
            acc3.z = fmaf(w3, v3.z, acc3.z); acc3.w = fmaf(w3, v3.w, acc3.w);
        }
        for (; r < end; r += 4) {
            float w = sw[r - start] * inv;
            float4 v = *(const float4*)(x + (size_t)r * DIM + c4);
            acc0.x = fmaf(w, v.x, acc0.x); acc0.y = fmaf(w, v.y, acc0.y);
            acc0.z = fmaf(w, v.z, acc0.z); acc0.w = fmaf(w, v.w, acc0.w);
        }
    } else {
        for (int base = start; base < end; base += 1024) {
            int mlen = end - base; if (mlen > 1024) mlen = 1024;
            __syncthreads();
            for (int j = tid; j < mlen; j += 256) sw[j] = __expf(g_scores[base + j] - M);
            __syncthreads();
            for (int r = base + rg; r < base + mlen; r += 4) {
                float w = sw[r - base] * inv;
                float4 v = *(const float4*)(x + (size_t)r * DIM + c4);
                acc0.x = fmaf(w, v.x, acc0.x); acc0.y = fmaf(w, v.y, acc0.y);
                acc0.z = fmaf(w, v.z, acc0.z); acc0.w = fmaf(w, v.w, acc0.w);
            }
        }
    }

    acc0.x = (acc0.x + acc1.x) + (acc2.x + acc3.x);
    acc0.y = (acc0.y + acc1.y) + (acc2.y + acc3.y);
    acc0.z = (acc0.z + acc1.z) + (acc2.z + acc3.z);
    acc0.w = (acc0.w + acc1.w) + (acc2.w + acc3.w);

    __syncthreads();
    sred[rg][c4 + 0] = acc0.x;
    sred[rg][c4 + 1] = acc0.y;
    sred[rg][c4 + 2] = acc0.z;
    sred[rg][c4 + 3] = acc0.w;
    __syncthreads();
    float v = sred[0][tid] + sred[1][tid] + sred[2][tid] + sred[3][tid];
    out[g * DIM + tid] = v;
}

// ---------------------------------------------------------------------------
extern "C" void kernel_launch(void* const* d_in, const int* in_sizes, int n_in,
                              void* d_out, int out_size) {
    const float* x     = (const float*)d_in[0];
    const int*   batch = (const int*)d_in[1];
    // d_in[2] = num_graphs (constant 2048, unused)
    const float* W1 = (const float*)d_in[3];
    const float* b1 = (const float*)d_in[4];
    const float* W2 = (const float*)d_in[5];
    const float* b2 = (const float*)d_in[6];
    float* out = (float*)d_out;

    cudaFuncSetAttribute(score_kernel, cudaFuncAttributeMaxDynamicSharedMemorySize, SMEM_BYTES);
    score_kernel<<<SGRID, 256, SMEM_BYTES>>>(x, W1, b1, W2, b2);
    pool_kernel<<<NGRAPH, 256>>>(batch, x, out);
}

// round 10
// speedup vs baseline: 1.2472x; 1.0035x over previous
#include <cuda_runtime.h>
#include <cstdint>

#define N_NODES 262144
#define DIM     256
#define HID     128
#define NGRAPH  2048
#define NTILES  2048          // N_NODES / 128
#define SGRID   152
#define CHUNK   256           // rows per stream_pool block
#define PBLK    (N_NODES / CHUNK)   // 1024

// smem layout for score kernel
#define WSF_BYTES   131072    // uint32 wsf[32 ksteps][16 ntiles][32 lanes][2]
#define XS_BYTES    36864     // float xs[2][128][36]
#define B1F_BYTES   4096      // float b1f[16][32][2]
#define W2F_BYTES   4096
#define SMEM_BYTES  (WSF_BYTES + XS_BYTES + B1F_BYTES + W2F_BYTES)   // 176128

__device__ float g_scores[N_NODES];
__device__ float g_M[NGRAPH];
__device__ float g_invS[NGRAPH];

// ---------------------------------------------------------------------------
__device__ __forceinline__ uint32_t f2tf32(float f) {
    uint32_t u;
    asm("cvt.rna.tf32.f32 %0, %1;" : "=r"(u) : "f"(f));
    return u;
}

__device__ __forceinline__ void mma_tf32(float* c,
                                         uint32_t a0, uint32_t a1, uint32_t a2, uint32_t a3,
                                         uint32_t b0, uint32_t b1) {
    asm volatile(
        "mma.sync.aligned.m16n8k8.row.col.f32.tf32.tf32.f32 "
        "{%0,%1,%2,%3}, {%4,%5,%6,%7}, {%8,%9}, {%0,%1,%2,%3};"
        : "+f"(c[0]), "+f"(c[1]), "+f"(c[2]), "+f"(c[3])
        : "r"(a0), "r"(a1), "r"(a2), "r"(a3), "r"(b0), "r"(b1));
}

__device__ __forceinline__ int lower_bound_i(const int* __restrict__ b, int n, int key) {
    int lo = 0, hi = n;
    while (lo < hi) {
        int mid = (lo + hi) >> 1;
        if (b[mid] < key) lo = mid + 1; else hi = mid;
    }
    return lo;
}

__device__ __forceinline__ float warp_max(float v) {
    #pragma unroll
    for (int o = 16; o; o >>= 1) v = fmaxf(v, __shfl_xor_sync(0xffffffffu, v, o));
    return v;
}
__device__ __forceinline__ float warp_sum(float v) {
    #pragma unroll
    for (int o = 16; o; o >>= 1) v += __shfl_xor_sync(0xffffffffu, v, o);
    return v;
}

// ---------------------------------------------------------------------------
// Kernel 1: scores[i] = b2 + sum_j W2[j] * relu(b1[j] + sum_k x[i][k]*W1[k][j])
// (R5 structure: 128-row tiles, 16 rows/warp, register-prefetch double buffer.)
// ---------------------------------------------------------------------------
__global__ void __launch_bounds__(256, 1)
score_kernel(const float* __restrict__ x,
             const float* __restrict__ W1,
             const float* __restrict__ b1,
             const float* __restrict__ W2,
             const float* __restrict__ b2) {
    extern __shared__ __align__(16) unsigned char smem[];
    uint32_t* wsf = (uint32_t*)smem;                          // [ks][nt][lane][2]
    float*    xs  = (float*)(smem + WSF_BYTES);               // [2][128][36]
    float*    b1f = (float*)(smem + WSF_BYTES + XS_BYTES);    // [nt][lane][2]
    float*    w2f = b1f + 1024;

    const int tid  = threadIdx.x;
    const int lane = tid & 31;
    const int warp = tid >> 5;

    // --- stage W1 as tf32 B-fragments: b0 = W1[ks*8 + (lane&3)][nt*8 + lane/4]
    for (int i = tid; i < 32 * 16 * 32; i += 256) {
        int l = i & 31, nt = (i >> 5) & 15, ks = i >> 9;
        int col = nt * 8 + (l >> 2);
        int r0  = ks * 8 + (l & 3);
        wsf[2 * i + 0] = f2tf32(W1[r0 * HID + col]);
        wsf[2 * i + 1] = f2tf32(W1[(r0 + 4) * HID + col]);
    }
    // --- stage b1 / W2 in C-fragment column order: cols nt*8 + 2*(lane&3) {,+1}
    for (int i = tid; i < 16 * 32; i += 256) {
        int l = i & 31, nt = i >> 5;
        int c0 = nt * 8 + 2 * (l & 3);
        b1f[2 * i + 0] = b1[c0];
        b1f[2 * i + 1] = b1[c0 + 1];
        w2f[2 * i + 0] = W2[c0];
        w2f[2 * i + 1] = W2[c0 + 1];
    }
    const float b2v = b2[0];

    const int grid = gridDim.x;
    const int srow = tid >> 3;        // staging row 0..31 (thread covers +0,+32,+64,+96)
    const int scol = (tid & 7) * 4;   // staging col offset within 32-wide chunk

    // --- prologue: chunk 0 of first tile into buffer 0
    {
        int t0 = blockIdx.x;
        if (t0 < NTILES) {
            #pragma unroll
            for (int q = 0; q < 4; q++) {
                int row = srow + 32 * q;
                float4 v = *(const float4*)(x + (t0 * 128 + row) * DIM + scol);
                *(float4*)(xs + row * 36 + scol) = v;
            }
        }
    }
    __syncthreads();

    const int rA = warp * 16 + (lane >> 2);   // A-frag row within tile
    const int t4 = lane & 3;

    for (int tile = blockIdx.x; tile < NTILES; tile += grid) {
        float c[16][4];
        #pragma unroll
        for (int nt = 0; nt < 16; nt++)
            #pragma unroll
            for (int q = 0; q < 4; q++) c[nt][q] = 0.0f;

        #pragma unroll 1
        for (int kc = 0; kc < 8; kc++) {
            // prefetch next chunk (next tile's chunk 0 when kc==7)
            int ptile = (kc < 7) ? tile : (tile + grid);
            int pkc   = (kc + 1) & 7;
            bool pv   = (ptile < NTILES);
            float4 pr[4];
            if (pv) {
                #pragma unroll
                for (int q = 0; q < 4; q++) {
                    int row = srow + 32 * q;
                    pr[q] = *(const float4*)(x + (ptile * 128 + row) * DIM + pkc * 32 + scol);
                }
            }

            // compute 4 k-steps from current buffer
            const float* xb = xs + (kc & 1) * (128 * 36);
            #pragma unroll
            for (int ksl = 0; ksl < 4; ksl++) {
                int k0 = ksl * 8;
                uint32_t a0 = f2tf32(xb[rA * 36 + k0 + t4]);
                uint32_t a1 = f2tf32(xb[(rA + 8) * 36 + k0 + t4]);
                uint32_t a2 = f2tf32(xb[rA * 36 + k0 + t4 + 4]);
                uint32_t a3 = f2tf32(xb[(rA + 8) * 36 + k0 + t4 + 4]);
                int ks = kc * 4 + ksl;
                const uint32_t* wb = wsf + (ks * 512 + lane) * 2;
                #pragma unroll
                for (int nt = 0; nt < 16; nt++) {
                    uint32_t bb0 = wb[nt * 64];
                    uint32_t bb1 = wb[nt * 64 + 1];
                    mma_tf32(c[nt], a0, a1, a2, a3, bb0, bb1);
                }
            }

            // store prefetched chunk into other buffer
            if (pv) {
                float* xd = xs + ((kc + 1) & 1) * (128 * 36);
                #pragma unroll
                for (int q = 0; q < 4; q++) {
                    int row = srow + 32 * q;
                    *(float4*)(xd + row * 36 + scol) = pr[q];
                }
            }
            __syncthreads();
        }

        // --- epilogue: bias + relu + dot with W2, reduce over j
        float p0 = 0.0f, p8 = 0.0f;
        #pragma unroll
        for (int nt = 0; nt < 16; nt++) {
            int bi = (nt * 32 + lane) * 2;
            float q0 = b1f[bi], q1 = b1f[bi + 1];
            float w0 = w2f[bi], w1 = w2f[bi + 1];
            p0 += fmaxf(c[nt][0] + q0, 0.0f) * w0 + fmaxf(c[nt][1] + q1, 0.0f) * w1;
            p8 += fmaxf(c[nt][2] + q0, 0.0f) * w0 + fmaxf(c[nt][3] + q1, 0.0f) * w1;
        }
        p0 += __shfl_xor_sync(0xffffffffu, p0, 1);
        p0 += __shfl_xor_sync(0xffffffffu, p0, 2);
        p8 += __shfl_xor_sync(0xffffffffu, p8, 1);
        p8 += __shfl_xor_sync(0xffffffffu, p8, 2);
        if ((lane & 3) == 0) {
            int row = tile * 128 + warp * 16 + (lane >> 2);
            g_scores[row]     = p0 + b2v;
            g_scores[row + 8] = p8 + b2v;
        }
    }
}

// ---------------------------------------------------------------------------
// Kernel 2: per-graph softmax stats (max, 1/sum_exp); also zero out[].
// Scores are L2-resident (1 MB). One block per graph.
// ---------------------------------------------------------------------------
__global__ void __launch_bounds__(256)
stats_kernel(const int* __restrict__ batch, float* __restrict__ out) {
    const int g = blockIdx.x;
    const int tid = threadIdx.x;
    const int lane = tid & 31, wid = tid >> 5;
    __shared__ int sse[2];
    __shared__ float red[8];

    out[g * DIM + tid] = 0.0f;   // zero output (poisoned by harness)

    if (tid < 2) sse[tid] = lower_bound_i(batch, N_NODES, g + tid);
    __syncthreads();
    const int start = sse[0], end = sse[1];

    float m = -1e30f;
    for (int i = start + tid; i < end; i += 256) m = fmaxf(m, g_scores[i]);
    m = warp_max(m);
    if (lane == 0) red[wid] = m;
    __syncthreads();
    if (wid == 0) {
        float v = (lane < 8) ? red[lane] : -1e30f;
        v = warp_max(v);
        if (lane == 0) red[0] = v;
    }
    __syncthreads();
    const float M = red[0];
    __syncthreads();

    float s = 0.0f;
    for (int i = start + tid; i < end; i += 256) s += __expf(g_scores[i] - M);
    s = warp_sum(s);
    if (lane == 0) red[wid] = s;
    __syncthreads();
    if (wid == 0) {
        float v = (lane < 8) ? red[lane] : 0.0f;
        v = warp_sum(v);
        if (lane == 0) {
            g_M[g] = M;
            g_invS[g] = (end > start) ? (1.0f / v) : 0.0f;
        }
    }
}

// ---------------------------------------------------------------------------
// Kernel 3: streaming weighted pooling. Uniform 256-row chunks in address
// order (perfect coalescing + balance). Per-chunk weights staged in smem;
// 16-row fast path (sorted batch) keeps 4 float4 loads in flight; segment
// boundaries flushed with atomicAdd (out pre-zeroed).
// ---------------------------------------------------------------------------
__global__ void __launch_bounds__(256)
stream_pool(const int* __restrict__ batch,
            const float* __restrict__ x,
            float* __restrict__ out) {
    const int base = blockIdx.x * CHUNK;
    const int tid = threadIdx.x;
    __shared__ __align__(16) float sw[CHUNK];
    __shared__ int sb[CHUNK];

    // phase A: weights for this chunk
    {
        int r = base + tid;
        int b = batch[r];
        sb[tid] = b;
        sw[tid] = __expf(g_scores[r] - g_M[b]) * g_invS[b];
    }
    __syncthreads();

    const int c4 = (tid & 63) * 4;    // column group
    const int rg = tid >> 6;          // row offset 0..3
    const float* xp0 = x + (size_t)base * DIM + c4;

    float4 a0 = make_float4(0.f, 0.f, 0.f, 0.f);
    float4 a1 = make_float4(0.f, 0.f, 0.f, 0.f);
    float4 a2 = make_float4(0.f, 0.f, 0.f, 0.f);
    float4 a3 = make_float4(0.f, 0.f, 0.f, 0.f);
    int cur = sb[rg];

    #define FLUSH_ACC() do {                                             \
        float fx = (a0.x + a1.x) + (a2.x + a3.x);                        \
        float fy = (a0.y + a1.y) + (a2.y + a3.y);                        \
        float fz = (a0.z + a1.z) + (a2.z + a3.z);                        \
        float fw = (a0.w + a1.w) + (a2.w + a3.w);                        \
        float* op = out + (size_t)cur * DIM + c4;                        \
        atomicAdd(op + 0, fx); atomicAdd(op + 1, fy);                    \
        atomicAdd(op + 2, fz); atomicAdd(op + 3, fw);                    \
        a0 = a1 = a2 = a3 = make_float4(0.f, 0.f, 0.f, 0.f);             \
    } while (0)

    #pragma unroll 1
    for (int j = rg; j < CHUNK; j += 16) {
        if (sb[j + 12] == cur) {
            // fast path: all 4 rows belong to cur -> 4 independent loads
            float w0 = sw[j], w1 = sw[j + 4], w2 = sw[j + 8], w3 = sw[j + 12];
            float4 v0 = *(const float4*)(xp0 + (size_t)j * DIM);
            float4 v1 = *(const float4*)(xp0 + (size_t)(j + 4) * DIM);
            float4 v2 = *(const float4*)(xp0 + (size_t)(j + 8) * DIM);
            float4 v3 = *(const float4*)(xp0 + (size_t)(j + 12) * DIM);
            a0.x = fmaf(w0, v0.x, a0.x); a0.y = fmaf(w0, v0.y, a0.y);
            a0.z = fmaf(w0, v0.z, a0.z); a0.w = fmaf(w0, v0.w, a0.w);
            a1.x = fmaf(w1, v1.x, a1.x); a1.y = fmaf(w1, v1.y, a1.y);
            a1.z = fmaf(w1, v1.z, a1.z); a1.w = fmaf(w1, v1.w, a1.w);
            a2.x = fmaf(w2, v2.x, a2.x); a2.y = fmaf(w2, v2.y, a2.y);
            a2.z = fmaf(w2, v2.z, a2.z); a2.w = fmaf(w2, v2.w, a2.w);
            a3.x = fmaf(w3, v3.x, a3.x); a3.y = fmaf(w3, v3.y, a3.y);
            a3.z = fmaf(w3, v3.z, a3.z); a3.w = fmaf(w3, v3.w, a3.w);
        } else {
            // slow path: graph boundary inside this 16-row group
            #pragma unroll
            for (int t = 0; t < 4; t++) {
                int jj = j + 4 * t;
                int b = sb[jj];
                if (b != cur) { FLUSH_ACC(); cur = b; }
                float w = sw[jj];
                float4 v = *(const float4*)(xp0 + (size_t)jj * DIM);
                a0.x = fmaf(w, v.x, a0.x); a0.y = fmaf(w, v.y, a0.y);
                a0.z = fmaf(w, v.z, a0.z); a0.w = fmaf(w, v.w, a0.w);
            }
        }
    }
    FLUSH_ACC();
    #undef FLUSH_ACC
}

// ---------------------------------------------------------------------------
extern "C" void kernel_launch(void* const* d_in, const int* in_sizes, int n_in,
                              void* d_out, int out_size) {
    const float* x     = (const float*)d_in[0];
    const int*   batch = (const int*)d_in[1];
    // d_in[2] = num_graphs (constant 2048, unused)
    const float* W1 = (const float*)d_in[3];
    const float* b1 = (const float*)d_in[4];
    const float* W2 = (const float*)d_in[5];
    const float* b2 = (const float*)d_in[6];
    float* out = (float*)d_out;

    cudaFuncSetAttribute(score_kernel, cudaFuncAttributeMaxDynamicSharedMemorySize, SMEM_BYTES);
    score_kernel<<<SGRID, 256, SMEM_BYTES>>>(x, W1, b1, W2, b2);
    stats_kernel<<<NGRAPH, 256>>>(batch, out);
    stream_pool<<<PBLK, 256>>>(batch, x, out);
}